// round 11
// baseline (speedup 1.0000x reference)
#include <cuda_runtime.h>
#include <cuda_bf16.h>
#include <cuda_fp16.h>
#include <cstdint>

#define BB 4
#define QN 128
#define KN 1024
#define DD 512     // DQ == DK == DV
#define HH 256
#define AVSPLIT 4
#define AVKS (KN / AVSPLIT)    // 256

#define MROWS (BB * QN + BB * KN)   // 4608 combined projection rows

// ---------------- Scratch (__device__ globals; no allocs allowed) ----------
__device__ float g_scores[BB * QN * KN];             // [512][1024] f32 scores
__device__ float g_avp[AVSPLIT][BB * QN * DD];       // split-K partials

__device__ __half2 g_qp2[BB * QN * HH / 2];          // qp as h-paired half2
__device__ __half2 g_kp2[BB * KN * HH / 2];          // kp as h-paired half2

__device__ __nv_bfloat16 g_ab_hi[MROWS * DD];        // combined Q|K rows, bf16 hi
__device__ __nv_bfloat16 g_ab_lo[MROWS * DD];
__device__ __nv_bfloat16 g_wt_hi[2][HH * DD];        // W^T bf16 hi  [256][512]
__device__ __nv_bfloat16 g_wt_lo[2][HH * DD];

__device__ __nv_bfloat16 g_at_hi[BB * QN * KN];      // attn bf16 hi [512][1024]
__device__ __nv_bfloat16 g_at_lo[BB * QN * KN];
__device__ __nv_bfloat16 g_vt_hi[BB * DD * KN];      // V^T bf16 hi [b][n][k]
__device__ __nv_bfloat16 g_vt_lo[BB * DD * KN];

// ---------------------------------------------------------------------------
// HMMA helpers (baseline PTX, plain sm_103 target)
// ---------------------------------------------------------------------------
__device__ __forceinline__ uint32_t smem_u32(const void* p) {
    uint32_t a;
    asm("{ .reg .u64 t; cvta.to.shared.u64 t, %1; cvt.u32.u64 %0, t; }" : "=r"(a) : "l"(p));
    return a;
}
__device__ __forceinline__ void ldsm_x4(uint32_t& r0, uint32_t& r1, uint32_t& r2,
                                        uint32_t& r3, uint32_t addr) {
    asm volatile("ldmatrix.sync.aligned.m8n8.x4.shared.b16 {%0,%1,%2,%3}, [%4];"
                 : "=r"(r0), "=r"(r1), "=r"(r2), "=r"(r3) : "r"(addr));
}
__device__ __forceinline__ void mma_bf16(float* d, const uint32_t* a, const uint32_t* b) {
    asm volatile(
        "mma.sync.aligned.m16n8k16.row.col.f32.bf16.bf16.f32 "
        "{%0,%1,%2,%3}, {%4,%5,%6,%7}, {%8,%9}, {%0,%1,%2,%3};"
        : "+f"(d[0]), "+f"(d[1]), "+f"(d[2]), "+f"(d[3])
        : "r"(a[0]), "r"(a[1]), "r"(a[2]), "r"(a[3]), "r"(b[0]), "r"(b[1]));
}

// ---------------------------------------------------------------------------
// Conversion: queries|keys rows -> bf16 hi/lo (combined [4608][512])
// ---------------------------------------------------------------------------
__global__ __launch_bounds__(256) void conv_ab(
    const float* __restrict__ queries, const float* __restrict__ keys)
{
    const int i4 = blockIdx.x * 256 + threadIdx.x;
    const int QF4 = BB * QN * DD / 4;
    float4 v = (i4 < QF4) ? ((const float4*)queries)[i4]
                          : ((const float4*)keys)[i4 - QF4];
    float s[4] = {v.x, v.y, v.z, v.w};
    __nv_bfloat16 h[4], l[4];
    #pragma unroll
    for (int j = 0; j < 4; j++) {
        h[j] = __float2bfloat16(s[j]);
        l[j] = __float2bfloat16(s[j] - __bfloat162float(h[j]));
    }
    __nv_bfloat162* oh = (__nv_bfloat162*)g_ab_hi;
    __nv_bfloat162* ol = (__nv_bfloat162*)g_ab_lo;
    oh[i4 * 2 + 0] = __halves2bfloat162(h[0], h[1]);
    oh[i4 * 2 + 1] = __halves2bfloat162(h[2], h[3]);
    ol[i4 * 2 + 0] = __halves2bfloat162(l[0], l[1]);
    ol[i4 * 2 + 1] = __halves2bfloat162(l[2], l[3]);
}

// ---------------------------------------------------------------------------
// Conversion: W[512][256] -> W^T bf16 hi/lo [256][512] (Wq z=0, Wk z=1)
// ---------------------------------------------------------------------------
__global__ __launch_bounds__(256) void conv_w(
    const float* __restrict__ Wq, const float* __restrict__ Wk)
{
    const int mat = blockIdx.z;
    const float* W = mat ? Wk : Wq;
    const int kt = blockIdx.x * 32;
    const int nt = blockIdx.y * 32;
    __shared__ float t[32][33];

    const int tx = threadIdx.x & 31;
    const int ty = threadIdx.x >> 5;
    #pragma unroll
    for (int i = 0; i < 4; i++) {
        int r = ty + i * 8;
        t[r][tx] = W[(size_t)(kt + r) * HH + nt + tx];
    }
    __syncthreads();
    #pragma unroll
    for (int i = 0; i < 4; i++) {
        int n = ty + i * 8;
        float v = t[tx][n];
        __nv_bfloat16 h = __float2bfloat16(v);
        __nv_bfloat16 l = __float2bfloat16(v - __bfloat162float(h));
        g_wt_hi[mat][(size_t)(nt + n) * DD + kt + tx] = h;
        g_wt_lo[mat][(size_t)(nt + n) * DD + kt + tx] = l;
    }
}

// ---------------------------------------------------------------------------
// Conversion: V[b][k][n] f32 -> V^T[b][n][k] bf16 hi/lo (32x32 tile transpose)
// grid (32 kt, 16 nt, 4 b) x 256
// ---------------------------------------------------------------------------
__global__ __launch_bounds__(256) void conv_v(const float* __restrict__ V)
{
    const int b  = blockIdx.z;
    const int kt = blockIdx.x * 32;
    const int nt = blockIdx.y * 32;
    __shared__ float t[32][33];

    const int tx = threadIdx.x & 31;
    const int ty = threadIdx.x >> 5;
    #pragma unroll
    for (int i = 0; i < 4; i++) {
        int r = ty + i * 8;   // k within tile
        t[r][tx] = V[((size_t)b * KN + kt + r) * DD + nt + tx];
    }
    __syncthreads();
    #pragma unroll
    for (int i = 0; i < 4; i++) {
        int n = ty + i * 8;   // n within tile
        float v = t[tx][n];   // = V[kt+tx][nt+n]
        __nv_bfloat16 h = __float2bfloat16(v);
        __nv_bfloat16 l = __float2bfloat16(v - __bfloat162float(h));
        size_t o = ((size_t)b * DD + nt + n) * KN + kt + tx;
        g_vt_hi[o] = h;
        g_vt_lo[o] = l;
    }
}

// ---------------------------------------------------------------------------
// HMMA projection GEMM: [128,64] tile per CTA, 3-term bf16 hi/lo split.
// Epilogue writes h-paired half2 to g_qp2 / g_kp2. grid (36,4) x 256.
// ---------------------------------------------------------------------------
#define ASTRIDE 24    // bf16 units per smem row (48 B)

__global__ __launch_bounds__(256) void proj_hmma(const int* __restrict__ vlen)
{
    __shared__ __align__(16) __nv_bfloat16 sA[2][2][128 * ASTRIDE];
    __shared__ __align__(16) __nv_bfloat16 sB[2][2][64 * ASTRIDE];

    const int tid  = threadIdx.x;
    const int wid  = tid >> 5;
    const int lane = tid & 31;

    const int m0 = blockIdx.x * 128;
    const int n0 = blockIdx.y * 64;

    const __nv_bfloat16* wt_hi;
    const __nv_bfloat16* wt_lo;
    __half2* C2;
    int crow;
    if (m0 < BB * QN) {
        wt_hi = g_wt_hi[0]; wt_lo = g_wt_lo[0]; C2 = g_qp2; crow = m0;
    } else {
        int mk = m0 - BB * QN;
        int b = mk >> 10;
        if ((mk & 1023) >= vlen[b]) return;
        wt_hi = g_wt_hi[1]; wt_lo = g_wt_lo[1]; C2 = g_kp2; crow = mk;
    }

    const int warp_m = wid & 3;
    const int warp_n = wid >> 2;

    const int arow  = tid >> 1;
    const int ahalf = tid & 1;
    const int brow  = (tid & 127) >> 1;
    const int bterm = tid >> 7;

    const int a_r  = (lane & 7) + ((lane >> 3) & 1) * 8;
    const int a_c  = (lane >> 4) * 8;
    const int b_r  = (lane & 7) + ((lane >> 4) & 1) * 8;
    const int b_c  = ((lane >> 3) & 1) * 8;

    float acc[2][4][4] = {};
    float4 pah, pal, pbx;

    const __nv_bfloat16* wsel = bterm ? wt_lo : wt_hi;

    pah = *(const float4*)&g_ab_hi[(size_t)(m0 + arow) * DD + ahalf * 8];
    pal = *(const float4*)&g_ab_lo[(size_t)(m0 + arow) * DD + ahalf * 8];
    pbx = *(const float4*)&wsel[(size_t)(n0 + brow) * DD + ahalf * 8];
    *(float4*)&sA[0][0][arow * ASTRIDE + ahalf * 8] = pah;
    *(float4*)&sA[0][1][arow * ASTRIDE + ahalf * 8] = pal;
    *(float4*)&sB[0][bterm][brow * ASTRIDE + ahalf * 8] = pbx;
    __syncthreads();

    int buf = 0;
    #pragma unroll 1
    for (int c = 0; c < 32; c++) {
        if (c + 1 < 32) {
            int k0 = (c + 1) * 16;
            pah = *(const float4*)&g_ab_hi[(size_t)(m0 + arow) * DD + k0 + ahalf * 8];
            pal = *(const float4*)&g_ab_lo[(size_t)(m0 + arow) * DD + k0 + ahalf * 8];
            pbx = *(const float4*)&wsel[(size_t)(n0 + brow) * DD + k0 + ahalf * 8];
        }

        uint32_t Ah[2][4], Al[2][4], Bh[4][2], Bl[4][2];
        #pragma unroll
        for (int mt = 0; mt < 2; mt++) {
            uint32_t ra = smem_u32(&sA[buf][0][(warp_m * 32 + mt * 16 + a_r) * ASTRIDE + a_c]);
            ldsm_x4(Ah[mt][0], Ah[mt][1], Ah[mt][2], Ah[mt][3], ra);
            uint32_t rl = smem_u32(&sA[buf][1][(warp_m * 32 + mt * 16 + a_r) * ASTRIDE + a_c]);
            ldsm_x4(Al[mt][0], Al[mt][1], Al[mt][2], Al[mt][3], rl);
        }
        #pragma unroll
        for (int p = 0; p < 2; p++) {
            uint32_t rb = smem_u32(&sB[buf][0][(warp_n * 32 + p * 16 + b_r) * ASTRIDE + b_c]);
            ldsm_x4(Bh[p * 2][0], Bh[p * 2][1], Bh[p * 2 + 1][0], Bh[p * 2 + 1][1], rb);
            uint32_t rc = smem_u32(&sB[buf][1][(warp_n * 32 + p * 16 + b_r) * ASTRIDE + b_c]);
            ldsm_x4(Bl[p * 2][0], Bl[p * 2][1], Bl[p * 2 + 1][0], Bl[p * 2 + 1][1], rc);
        }
        #pragma unroll
        for (int mt = 0; mt < 2; mt++)
            #pragma unroll
            for (int nt = 0; nt < 4; nt++) {
                mma_bf16(acc[mt][nt], Ah[mt], Bh[nt]);
                mma_bf16(acc[mt][nt], Ah[mt], Bl[nt]);
                mma_bf16(acc[mt][nt], Al[mt], Bh[nt]);
            }

        if (c + 1 < 32) {
            int nb = buf ^ 1;
            *(float4*)&sA[nb][0][arow * ASTRIDE + ahalf * 8] = pah;
            *(float4*)&sA[nb][1][arow * ASTRIDE + ahalf * 8] = pal;
            *(float4*)&sB[nb][bterm][brow * ASTRIDE + ahalf * 8] = pbx;
            __syncthreads();
            buf = nb;
        }
    }

    const int tq = lane >> 2;
    const int tr = lane & 3;
    #pragma unroll
    for (int mt = 0; mt < 2; mt++)
        #pragma unroll
        for (int nt = 0; nt < 4; nt++) {
            int m = crow + warp_m * 32 + mt * 16 + tq;
            int hp = (n0 + warp_n * 32 + nt * 8 + tr * 2) >> 1;
            C2[(size_t)m * (HH / 2) + hp] =
                __floats2half2_rn(acc[mt][nt][0], acc[mt][nt][1]);
            C2[(size_t)(m + 8) * (HH / 2) + hp] =
                __floats2half2_rn(acc[mt][nt][2], acc[mt][nt][3]);
        }
}

// ---------------------------------------------------------------------------
// Scores (f16x2, wide LDS): s = sum_h wv[h] * tanh(qp + kp)
// block 256 = 8 warps (one q each); each lane: 2 k (2*lane, 2*lane+1).
// grid (k 16, q 16, b 4). f32 accumulate (precision).
// ---------------------------------------------------------------------------
__global__ __launch_bounds__(256) void scores_kernel(
    const float* __restrict__ wv, const int* __restrict__ vlen)
{
    const int b  = blockIdx.z;
    const int q0 = blockIdx.y * 8;
    const int k0 = blockIdx.x * 64;
    const int vl = vlen[b];
    if (k0 >= vl) return;

    __shared__ __align__(16) __half2 qs2[8][128];   // 4 KB
    __shared__ __align__(16) float   wvf[256];      // 1 KB (float4-loadable)
    __shared__ __align__(16) __half2 kst[128][66];  // ~33.8 KB transposed

    const int tid  = threadIdx.x;
    const int lane = tid & 31;
    const int w    = tid >> 5;

    const uint32_t* qp2 = (const uint32_t*)(g_qp2 + (size_t)(b * QN + q0) * 128);
    #pragma unroll
    for (int i = 0; i < 4; i++)
        ((uint32_t*)qs2)[tid + i * 256] = qp2[tid + i * 256];
    if (tid < 64) ((float4*)wvf)[tid] = ((const float4*)wv)[tid];

    // transposed kst load: 64 k-rows x 128 h-pairs (conflict-free pattern)
    {
        const __half2* kp2 = g_kp2 + (size_t)(b * KN + k0) * 128;
        const int kk = tid >> 2;
        const int q8 = tid & 3;
        #pragma unroll
        for (int j = 0; j < 8; j++) {
            int hpq = q8 + j * 4;
            float4 v = ((const float4*)(kp2 + (size_t)kk * 128))[hpq];
            const __half2* pv = (const __half2*)&v;
            #pragma unroll
            for (int r = 0; r < 4; r++)
                kst[hpq * 4 + r][kk] = pv[r];
        }
    }
    __syncthreads();

    const int q = w;
    float a00 = 0.f, a01 = 0.f, a10 = 0.f, a11 = 0.f;  // [k idx][chain]
    #pragma unroll 4
    for (int hp = 0; hp < 128; hp += 2) {
        uint2  qp_ = *(const uint2*)&qs2[q][hp];
        float4 wq  = *(const float4*)&wvf[hp * 2];
        float2 kp0 = *(const float2*)&kst[hp][2 * lane];
        float2 kp1 = *(const float2*)&kst[hp + 1][2 * lane];
        __half2 qv0 = *(__half2*)&qp_.x;
        __half2 qv1 = *(__half2*)&qp_.y;
        const __half2* k0v = (const __half2*)&kp0;
        const __half2* k1v = (const __half2*)&kp1;

        __half2 x00 = __hadd2(qv0, k0v[0]);   // hp,   k=2l
        __half2 x01 = __hadd2(qv0, k0v[1]);   // hp,   k=2l+1
        __half2 x10 = __hadd2(qv1, k1v[0]);   // hp+1, k=2l
        __half2 x11 = __hadd2(qv1, k1v[1]);   // hp+1, k=2l+1
        uint32_t t00, t01, t10, t11;
        asm("tanh.approx.f16x2 %0, %1;" : "=r"(t00) : "r"(*(uint32_t*)&x00));
        asm("tanh.approx.f16x2 %0, %1;" : "=r"(t01) : "r"(*(uint32_t*)&x01));
        asm("tanh.approx.f16x2 %0, %1;" : "=r"(t10) : "r"(*(uint32_t*)&x10));
        asm("tanh.approx.f16x2 %0, %1;" : "=r"(t11) : "r"(*(uint32_t*)&x11));
        float2 f00 = __half22float2(*(__half2*)&t00);
        float2 f01 = __half22float2(*(__half2*)&t01);
        float2 f10 = __half22float2(*(__half2*)&t10);
        float2 f11 = __half22float2(*(__half2*)&t11);
        a00 = fmaf(wq.x, f00.x, a00); a00 = fmaf(wq.y, f00.y, a00);
        a01 = fmaf(wq.x, f01.x, a01); a01 = fmaf(wq.y, f01.y, a01);
        a10 = fmaf(wq.z, f10.x, a10); a10 = fmaf(wq.w, f10.y, a10);
        a11 = fmaf(wq.z, f11.x, a11); a11 = fmaf(wq.w, f11.y, a11);
    }
    size_t row = (size_t)(b * QN + q0 + q) * KN;
    *(float2*)&g_scores[row + k0 + 2 * lane] = make_float2(a00 + a10, a01 + a11);
}

// ---------------------------------------------------------------------------
// Softmax: reads f32 scores, writes attn as bf16 hi/lo (masked -> exact 0).
// ---------------------------------------------------------------------------
__global__ __launch_bounds__(128) void softmax_kernel(const int* __restrict__ vlen)
{
    const int row  = blockIdx.x * 4 + (threadIdx.x >> 5);
    const int lane = threadIdx.x & 31;
    const int b    = row >> 7;
    const int vl   = vlen[b];
    const float* s = g_scores + (size_t)row * KN;

    float vals[32];
    float mx = -1e30f;
    #pragma unroll
    for (int i = 0; i < 32; i++) {
        int kk = lane + i * 32;
        float v = (kk < vl) ? s[kk] : -1e30f;
        vals[i] = v;
        mx = fmaxf(mx, v);
    }
    #pragma unroll
    for (int o = 16; o; o >>= 1) mx = fmaxf(mx, __shfl_xor_sync(0xffffffffu, mx, o));

    float sum = 0.f;
    #pragma unroll
    for (int i = 0; i < 32; i++) {
        float e = (vals[i] > -1e29f) ? __expf(vals[i] - mx) : 0.f;
        vals[i] = e;
        sum += e;
    }
    #pragma unroll
    for (int o = 16; o; o >>= 1) sum += __shfl_xor_sync(0xffffffffu, sum, o);

    float r = 1.f / sum;
    size_t base = (size_t)row * KN;
    #pragma unroll
    for (int i = 0; i < 32; i++) {
        float v = vals[i] * r;
        __nv_bfloat16 h = __float2bfloat16(v);
        g_at_hi[base + lane + i * 32] = h;
        g_at_lo[base + lane + i * 32] = __float2bfloat16(v - __bfloat162float(h));
    }
}

// ---------------------------------------------------------------------------
// AV GEMM (HMMA, split-K): partial[s][b][128][n0..n0+63] over k-slice s*256.
// A = attn bf16 hi/lo [128 x 1024], B = V^T bf16 hi/lo [n][k]. 3-term split.
// grid (n 8, s 4, b 4) x 256. Same fragment plumbing as proj_hmma.
// ---------------------------------------------------------------------------
__global__ __launch_bounds__(256) void av_hmma(const int* __restrict__ vlen)
{
    __shared__ __align__(16) __nv_bfloat16 sA[2][2][128 * ASTRIDE];
    __shared__ __align__(16) __nv_bfloat16 sB[2][2][64 * ASTRIDE];

    const int tid  = threadIdx.x;
    const int wid  = tid >> 5;
    const int lane = tid & 31;

    const int n0 = blockIdx.x * 64;
    const int s  = blockIdx.y;
    const int b  = blockIdx.z;
    const int vl = vlen[b];
    const int kcap = min(KN, (vl + 15) & ~15);
    const int kbeg = s * AVKS;
    const int kend = min(kbeg + AVKS, kcap);
    if (kbeg >= kend) return;
    const int ntile = (kend - kbeg) >> 4;

    const __nv_bfloat16* At_hi = g_at_hi + (size_t)b * QN * KN;
    const __nv_bfloat16* At_lo = g_at_lo + (size_t)b * QN * KN;
    const __nv_bfloat16* Vt_hi = g_vt_hi + (size_t)b * DD * KN;
    const __nv_bfloat16* Vt_lo = g_vt_lo + (size_t)b * DD * KN;
    float* C = g_avp[s] + (size_t)b * QN * DD;

    const int warp_m = wid & 3;
    const int warp_n = wid >> 2;

    const int arow  = tid >> 1;
    const int ahalf = tid & 1;
    const int brow  = (tid & 127) >> 1;
    const int bterm = tid >> 7;

    const int a_r  = (lane & 7) + ((lane >> 3) & 1) * 8;
    const int a_c  = (lane >> 4) * 8;
    const int b_r  = (lane & 7) + ((lane >> 4) & 1) * 8;
    const int b_c  = ((lane >> 3) & 1) * 8;

    float acc[2][4][4] = {};
    float4 pah, pal, pbx;

    const __nv_bfloat16* vsel = bterm ? Vt_lo : Vt_hi;

    pah = *(const float4*)&At_hi[(size_t)arow * KN + kbeg + ahalf * 8];
    pal = *(const float4*)&At_lo[(size_t)arow * KN + kbeg + ahalf * 8];
    pbx = *(const float4*)&vsel[(size_t)(n0 + brow) * KN + kbeg + ahalf * 8];
    *(float4*)&sA[0][0][arow * ASTRIDE + ahalf * 8] = pah;
    *(float4*)&sA[0][1][arow * ASTRIDE + ahalf * 8] = pal;
    *(float4*)&sB[0][bterm][brow * ASTRIDE + ahalf * 8] = pbx;
    __syncthreads();

    int buf = 0;
    #pragma unroll 1
    for (int c = 0; c < ntile; c++) {
        if (c + 1 < ntile) {
            int k0 = kbeg + (c + 1) * 16;
            pah = *(const float4*)&At_hi[(size_t)arow * KN + k0 + ahalf * 8];
            pal = *(const float4*)&At_lo[(size_t)arow * KN + k0 + ahalf * 8];
            pbx = *(const float4*)&vsel[(size_t)(n0 + brow) * KN + k0 + ahalf * 8];
        }

        uint32_t Ah[2][4], Al[2][4], Bh[4][2], Bl[4][2];
        #pragma unroll
        for (int mt = 0; mt < 2; mt++) {
            uint32_t ra = smem_u32(&sA[buf][0][(warp_m * 32 + mt * 16 + a_r) * ASTRIDE + a_c]);
            ldsm_x4(Ah[mt][0], Ah[mt][1], Ah[mt][2], Ah[mt][3], ra);
            uint32_t rl = smem_u32(&sA[buf][1][(warp_m * 32 + mt * 16 + a_r) * ASTRIDE + a_c]);
            ldsm_x4(Al[mt][0], Al[mt][1], Al[mt][2], Al[mt][3], rl);
        }
        #pragma unroll
        for (int p = 0; p < 2; p++) {
            uint32_t rb = smem_u32(&sB[buf][0][(warp_n * 32 + p * 16 + b_r) * ASTRIDE + b_c]);
            ldsm_x4(Bh[p * 2][0], Bh[p * 2][1], Bh[p * 2 + 1][0], Bh[p * 2 + 1][1], rb);
            uint32_t rc = smem_u32(&sB[buf][1][(warp_n * 32 + p * 16 + b_r) * ASTRIDE + b_c]);
            ldsm_x4(Bl[p * 2][0], Bl[p * 2][1], Bl[p * 2 + 1][0], Bl[p * 2 + 1][1], rc);
        }
        #pragma unroll
        for (int mt = 0; mt < 2; mt++)
            #pragma unroll
            for (int nt = 0; nt < 4; nt++) {
                mma_bf16(acc[mt][nt], Ah[mt], Bh[nt]);
                mma_bf16(acc[mt][nt], Ah[mt], Bl[nt]);
                mma_bf16(acc[mt][nt], Al[mt], Bh[nt]);
            }

        if (c + 1 < ntile) {
            int nb = buf ^ 1;
            *(float4*)&sA[nb][0][arow * ASTRIDE + ahalf * 8] = pah;
            *(float4*)&sA[nb][1][arow * ASTRIDE + ahalf * 8] = pal;
            *(float4*)&sB[nb][bterm][brow * ASTRIDE + ahalf * 8] = pbx;
            __syncthreads();
            buf = nb;
        }
    }

    const int tq = lane >> 2;
    const int tr = lane & 3;
    #pragma unroll
    for (int mt = 0; mt < 2; mt++)
        #pragma unroll
        for (int nt = 0; nt < 4; nt++) {
            int m = warp_m * 32 + mt * 16 + tq;
            int n = n0 + warp_n * 32 + nt * 8 + tr * 2;
            *(float2*)&C[(size_t)m * DD + n] =
                make_float2(acc[mt][nt][0], acc[mt][nt][1]);
            *(float2*)&C[(size_t)(m + 8) * DD + n] =
                make_float2(acc[mt][nt][2], acc[mt][nt][3]);
        }
}

// ---------------------------------------------------------------------------
// Reduce split-K partials into out.
// ---------------------------------------------------------------------------
__global__ __launch_bounds__(256) void av_reduce(
    float* __restrict__ out, const int* __restrict__ vlen)
{
    const int idx = blockIdx.x * 256 + threadIdx.x;
    const int perB = QN * DD / 4;
    const int b = idx / perB;
    const int vl = vlen[b];
    const int ns = min(AVSPLIT, (vl + AVKS - 1) / AVKS);

    float4 acc = ((const float4*)g_avp[0])[idx];
    for (int s = 1; s < ns; s++) {
        float4 p = ((const float4*)g_avp[s])[idx];
        acc.x += p.x; acc.y += p.y; acc.z += p.z; acc.w += p.w;
    }
    ((float4*)out)[idx] = acc;
}

// ---------------------------------------------------------------------------
extern "C" void kernel_launch(void* const* d_in, const int* in_sizes, int n_in,
                              void* d_out, int out_size)
{
    (void)in_sizes; (void)n_in; (void)out_size;
    const float* queries = (const float*)d_in[0];   // [4,128,512]
    const float* keys    = (const float*)d_in[1];   // [4,1024,512]
    const float* values  = (const float*)d_in[2];   // [4,1024,512]
    const int*   vlen    = (const int*)d_in[3];     // [4]
    const float* Wq      = (const float*)d_in[4];   // [512,256]
    const float* Wk      = (const float*)d_in[5];   // [512,256]
    const float* wv      = (const float*)d_in[6];   // [256]
    float* out = (float*)d_out;                     // [4,128,512]

    conv_ab<<<2304, 256>>>(queries, keys);
    conv_w<<<dim3(16, 8, 2), 256>>>(Wq, Wk);
    conv_v<<<dim3(32, 16, 4), 256>>>(values);
    proj_hmma<<<dim3(36, 4), 256>>>(vlen);
    scores_kernel<<<dim3(16, 16, 4), 256>>>(wv, vlen);
    softmax_kernel<<<128, 128>>>(vlen);
    av_hmma<<<dim3(8, AVSPLIT, BB), 256>>>(vlen);
    av_reduce<<<256, 256>>>(out, vlen);
}